// round 10
// baseline (speedup 1.0000x reference)
#include <cuda_runtime.h>
#include <cuda_fp16.h>
#include <stdint.h>

// ---------------- problem constants ----------------
static constexpr int MROWS = 8192;          // 16*512
static constexpr int FLAT  = 12544;         // 7*7*256
static constexpr int HID   = 1024;
static constexpr int NCLS  = 81;
static constexpr int NPAD  = 128;

// ---------------- scratch (__device__ globals; no allocs allowed) ----------
__device__ __half g_W1t[(size_t)HID * FLAT];   // [N,K] K-major
__device__ __half g_W2t[(size_t)HID * HID];
__device__ __half g_W3t[(size_t)NPAD * HID];   // rows 81..127 zero
__device__ __half g_H1[(size_t)MROWS * HID];
__device__ __half g_H2[(size_t)MROWS * HID];

// ---------------- helpers ----------------
__device__ __forceinline__ uint32_t smem_u32(const void* p) {
    uint32_t a;
    asm("{ .reg .u64 t; cvta.to.shared.u64 t, %1; cvt.u32.u64 %0, t; }" : "=r"(a) : "l"(p));
    return a;
}
#define SWZ(o) ((o) ^ (((o) >> 3) & 0x70))

__device__ __forceinline__ void cp16(uint32_t dst, const void* src) {
    asm volatile("cp.async.cg.shared.global [%0], [%1], 16;" :: "r"(dst), "l"(src) : "memory");
}
__device__ __forceinline__ void cp_commit() { asm volatile("cp.async.commit_group;" ::: "memory"); }
__device__ __forceinline__ void cp_wait1() { asm volatile("cp.async.wait_group 1;" ::: "memory"); }
__device__ __forceinline__ void cp_wait0() { asm volatile("cp.async.wait_group 0;" ::: "memory"); }

__device__ __forceinline__ void ldsm4(uint32_t (&r)[4], uint32_t addr) {
    asm volatile("ldmatrix.sync.aligned.m8n8.x4.shared.b16 {%0,%1,%2,%3}, [%4];"
        : "=r"(r[0]), "=r"(r[1]), "=r"(r[2]), "=r"(r[3]) : "r"(addr));
}
__device__ __forceinline__ void mma16816(float (&d)[4], const uint32_t (&a)[4],
                                         uint32_t b0, uint32_t b1) {
    asm volatile("mma.sync.aligned.m16n8k16.row.col.f32.f16.f16.f32 "
        "{%0,%1,%2,%3}, {%4,%5,%6,%7}, {%8,%9}, {%0,%1,%2,%3};"
        : "+f"(d[0]), "+f"(d[1]), "+f"(d[2]), "+f"(d[3])
        : "r"(a[0]), "r"(a[1]), "r"(a[2]), "r"(a[3]), "r"(b0), "r"(b1));
}

// W[K,N] fp32 -> Wt[Npad,K] fp16 (zero-pad n>=N). grid(Npad/32, K/32), block(32,8)
__global__ void cvt_trans(const float* __restrict__ W, __half* __restrict__ Wt, int K, int N) {
    __shared__ float t[32][33];
    int n0 = blockIdx.x * 32, k0 = blockIdx.y * 32;
    int tx = threadIdx.x, ty = threadIdx.y;
    #pragma unroll
    for (int i = 0; i < 32; i += 8) {
        int n = n0 + tx;
        t[ty + i][tx] = (n < N) ? W[(size_t)(k0 + ty + i) * N + n] : 0.f;
    }
    __syncthreads();
    #pragma unroll
    for (int i = 0; i < 32; i += 8)
        Wt[(size_t)(n0 + ty + i) * K + k0 + tx] = __float2half_rn(t[tx][ty + i]);
}

// ---------------- GEMM1 fused: C = relu(A32[M,K] @ Wt[N,K]^T + b) -> fp16 ----
// BM=128, BN=64, BK=64; 256 thr, 8 warps (4Mx2N), warp tile 32x32, acc=32.
// A: fp32 LDG 2 chunks ahead (32 staging regs) -> cvt -> STS fp16 (2-stage).
// B: 3-stage cp.async.  smem 56 KB -> 3 CTAs/SM.
__global__ void __launch_bounds__(256, 3)
gemm1_fused(const float* __restrict__ A, const __half* __restrict__ Wt,
            const float* __restrict__ bias, __half* __restrict__ outp) {
    constexpr int K = FLAT, KC = K / 64;
    constexpr int A_ST = 16384;                 // fp16 A stage bytes
    constexpr int B_ST = 8192;

    extern __shared__ char smem[];
    const uint32_t sbase = smem_u32(smem);      // A16: 2 stages, then B: 3 stages
    const uint32_t bbase = sbase + 2 * A_ST;

    const int tid = threadIdx.x, wid = tid >> 5, lid = tid & 31;
    const int m0 = blockIdx.y * 128, n0 = blockIdx.x * 64;
    const int wm = (wid >> 1) * 32, wn = (wid & 1) * 32;

    float acc[2][4][4];
    #pragma unroll
    for (int a = 0; a < 2; ++a)
        #pragma unroll
        for (int b = 0; b < 4; ++b)
            #pragma unroll
            for (int c = 0; c < 4; ++c) acc[a][b][c] = 0.f;

    float4 ra[4][2];                             // 32 staging regs
    auto ldgA = [&](int c) {
        #pragma unroll
        for (int i = 0; i < 4; ++i) {
            int op = tid + i * 256, row = op >> 3, seg = op & 7;
            const float4* p = (const float4*)(A + (size_t)(m0 + row) * K + (c << 6) + seg * 8);
            ra[i][0] = p[0]; ra[i][1] = p[1];
        }
    };
    auto stsA = [&](int s) {
        #pragma unroll
        for (int i = 0; i < 4; ++i) {
            int op = tid + i * 256, row = op >> 3, seg = op & 7;
            __half2 h0 = __floats2half2_rn(ra[i][0].x, ra[i][0].y);
            __half2 h1 = __floats2half2_rn(ra[i][0].z, ra[i][0].w);
            __half2 h2 = __floats2half2_rn(ra[i][1].x, ra[i][1].y);
            __half2 h3 = __floats2half2_rn(ra[i][1].z, ra[i][1].w);
            *(uint4*)(smem + s * A_ST + SWZ(row * 128 + seg * 16)) =
                make_uint4(*(uint32_t*)&h0, *(uint32_t*)&h1, *(uint32_t*)&h2, *(uint32_t*)&h3);
        }
    };
    auto ldB = [&](int c) {
        const uint32_t sB = bbase + (uint32_t)(c % 3) * B_ST;
        const __half* Bb = Wt + (size_t)n0 * K + (c << 6);
        #pragma unroll
        for (int i = 0; i < 2; ++i) {
            int op = tid + i * 256, row = op >> 3, seg = op & 7;
            cp16(sB + SWZ((uint32_t)(row * 128 + seg * 16)), Bb + (size_t)row * K + seg * 8);
        }
        cp_commit();
    };

    ldgA(0); stsA(0); ldgA(1);
    ldB(0); ldB(1);

    const int lrow = lid & 15, lkh = lid >> 4;
    for (int c = 0; c < KC; ++c) {
        if (c >= KC - 1) cp_wait0(); else cp_wait1();
        __syncthreads();
        if (c + 1 < KC) stsA((c + 1) & 1);      // convert chunk c+1 from regs
        if (c + 2 < KC) { ldgA(c + 2); ldB(c + 2); }
        const uint32_t sA = sbase + (uint32_t)(c & 1) * A_ST;
        const uint32_t sB = bbase + (uint32_t)(c % 3) * B_ST;
        #pragma unroll
        for (int k0 = 0; k0 < 64; k0 += 16) {
            uint32_t bfr[2][4];
            #pragma unroll
            for (int nn = 0; nn < 2; ++nn) {
                uint32_t off = (uint32_t)((wn + nn * 16 + lrow) * 128 + (k0 + lkh * 8) * 2);
                ldsm4(bfr[nn], sB + SWZ(off));
            }
            #pragma unroll
            for (int ms = 0; ms < 2; ++ms) {
                uint32_t afr[4];
                uint32_t off = (uint32_t)((wm + ms * 16 + lrow) * 128 + (k0 + lkh * 8) * 2);
                ldsm4(afr, sA + SWZ(off));
                #pragma unroll
                for (int ns = 0; ns < 4; ++ns)
                    mma16816(acc[ms][ns], afr, bfr[ns >> 1][ns & 1], bfr[ns >> 1][(ns & 1) + 2]);
            }
        }
    }

    #pragma unroll
    for (int ms = 0; ms < 2; ++ms) {
        const int r0 = m0 + wm + ms * 16 + (lid >> 2);
        #pragma unroll
        for (int ns = 0; ns < 4; ++ns) {
            const int col = n0 + wn + ns * 8 + 2 * (lid & 3);
            float bx = bias[col], by = bias[col + 1];
            *(__half2*)(outp + (size_t)r0 * HID + col) =
                __floats2half2_rn(fmaxf(acc[ms][ns][0] + bx, 0.f),
                                  fmaxf(acc[ms][ns][1] + by, 0.f));
            *(__half2*)(outp + (size_t)(r0 + 8) * HID + col) =
                __floats2half2_rn(fmaxf(acc[ms][ns][2] + bx, 0.f),
                                  fmaxf(acc[ms][ns][3] + by, 0.f));
        }
    }
}

// ---------------- HMMA GEMM (fp16 A): BM=128, BN=64, occ3, 3-stage ----------
// MODE 0: relu, fp16 out (stride HID).  MODE 1: mask, fp32 out (stride NCLS).
template <int MODE>
__global__ void __launch_bounds__(256, 3)
gemm_hmma(const __half* __restrict__ A, const __half* __restrict__ Wt,
          const float* __restrict__ bias, void* __restrict__ outp,
          const void* __restrict__ maskp, int K) {
    constexpr int A_BYTES = 128 * 128;
    constexpr int B_BYTES = 64 * 128;
    constexpr int STAGE   = A_BYTES + B_BYTES;   // 24 KB

    extern __shared__ char smem[];
    const uint32_t tiles = smem_u32(smem);

    const int tid = threadIdx.x, wid = tid >> 5, lid = tid & 31;
    const int m0 = blockIdx.y * 128, n0 = blockIdx.x * 64;
    const int wm = (wid >> 1) * 32, wn = (wid & 1) * 32;
    const int KC = K >> 6;

    float acc[2][4][4];
    #pragma unroll
    for (int a = 0; a < 2; ++a)
        #pragma unroll
        for (int b = 0; b < 4; ++b)
            #pragma unroll
            for (int c = 0; c < 4; ++c) acc[a][b][c] = 0.f;

    auto load_stage = [&](int c) {
        const uint32_t sA = tiles + (uint32_t)(c % 3) * STAGE, sB = sA + A_BYTES;
        const __half* Ab = A + (size_t)m0 * K + (c << 6);
        const __half* Bb = Wt + (size_t)n0 * K + (c << 6);
        #pragma unroll
        for (int i = 0; i < 4; ++i) {
            int op = tid + i * 256, row = op >> 3, seg = op & 7;
            cp16(sA + SWZ((uint32_t)(row * 128 + seg * 16)), Ab + (size_t)row * K + seg * 8);
        }
        #pragma unroll
        for (int i = 0; i < 2; ++i) {
            int op = tid + i * 256, row = op >> 3, seg = op & 7;
            cp16(sB + SWZ((uint32_t)(row * 128 + seg * 16)), Bb + (size_t)row * K + seg * 8);
        }
        cp_commit();
    };

    load_stage(0);
    load_stage(1);

    const int lrow = lid & 15, lkh = lid >> 4;
    for (int c = 0; c < KC; ++c) {
        if (c >= KC - 1) cp_wait0(); else cp_wait1();
        __syncthreads();
        if (c + 2 < KC) load_stage(c + 2);
        const uint32_t sA = tiles + (uint32_t)(c % 3) * STAGE, sB = sA + A_BYTES;
        #pragma unroll
        for (int k0 = 0; k0 < 64; k0 += 16) {
            uint32_t bfr[2][4];
            #pragma unroll
            for (int nn = 0; nn < 2; ++nn) {
                uint32_t off = (uint32_t)((wn + nn * 16 + lrow) * 128 + (k0 + lkh * 8) * 2);
                ldsm4(bfr[nn], sB + SWZ(off));
            }
            #pragma unroll
            for (int ms = 0; ms < 2; ++ms) {
                uint32_t afr[4];
                uint32_t off = (uint32_t)((wm + ms * 16 + lrow) * 128 + (k0 + lkh * 8) * 2);
                ldsm4(afr, sA + SWZ(off));
                #pragma unroll
                for (int ns = 0; ns < 4; ++ns)
                    mma16816(acc[ms][ns], afr, bfr[ns >> 1][ns & 1], bfr[ns >> 1][(ns & 1) + 2]);
            }
        }
    }

    int m_is_i8 = 0;
    if (MODE == 1) {
        const unsigned char* m8 = (const unsigned char*)maskp;
        bool i8 = false;
        for (int i = 1; i < 256; ++i)
            if ((i & 3) && m8[i]) i8 = true;
        m_is_i8 = i8 ? 1 : 0;
    }

    #pragma unroll
    for (int ms = 0; ms < 2; ++ms) {
        const int r0 = m0 + wm + ms * 16 + (lid >> 2);
        #pragma unroll
        for (int ns = 0; ns < 4; ++ns) {
            const int col = n0 + wn + ns * 8 + 2 * (lid & 3);
            if (MODE == 0) {
                float bx = bias[col], by = bias[col + 1];
                __half* o = (__half*)outp;
                *(__half2*)(o + (size_t)r0 * HID + col) =
                    __floats2half2_rn(fmaxf(acc[ms][ns][0] + bx, 0.f),
                                      fmaxf(acc[ms][ns][1] + by, 0.f));
                *(__half2*)(o + (size_t)(r0 + 8) * HID + col) =
                    __floats2half2_rn(fmaxf(acc[ms][ns][2] + bx, 0.f),
                                      fmaxf(acc[ms][ns][3] + by, 0.f));
            } else {
                float* o = (float*)outp;
                #pragma unroll
                for (int h = 0; h < 2; ++h) {
                    const int rr = r0 + h * 8;
                    float mv;
                    if (m_is_i8) mv = (((const unsigned char*)maskp)[rr] != 0) ? 1.f : 0.f;
                    else         mv = (((const int*)maskp)[rr] != 0) ? 1.f : 0.f;
                    if (col < NCLS)
                        o[(size_t)rr * NCLS + col] = (acc[ms][ns][2 * h] + bias[col]) * mv;
                    if (col + 1 < NCLS)
                        o[(size_t)rr * NCLS + col + 1] = (acc[ms][ns][2 * h + 1] + bias[col + 1]) * mv;
                }
            }
        }
    }
}

// ---------------- launcher ----------------
extern "C" void kernel_launch(void* const* d_in, const int* in_sizes, int n_in,
                              void* d_out, int out_size) {
    const float* feat = (const float*)d_in[0];
    const void*  mask = d_in[1];
    const float* W1 = (const float*)d_in[2]; const float* b1 = (const float*)d_in[3];
    const float* W2 = (const float*)d_in[4]; const float* b2 = (const float*)d_in[5];
    const float* W3 = (const float*)d_in[6]; const float* b3 = (const float*)d_in[7];

    void *pW1, *pW2, *pW3, *pH1, *pH2;
    cudaGetSymbolAddress(&pW1, g_W1t);
    cudaGetSymbolAddress(&pW2, g_W2t);
    cudaGetSymbolAddress(&pW3, g_W3t);
    cudaGetSymbolAddress(&pH1, g_H1);
    cudaGetSymbolAddress(&pH2, g_H2);

    constexpr int SMEM1 = 2 * 16384 + 3 * 8192;        // 56 KB (gemm1 fused)
    constexpr int SMEM  = 3 * (128 * 128 + 64 * 128);  // 72 KB (gemm2/3)
    cudaFuncSetAttribute(gemm1_fused,  cudaFuncAttributeMaxDynamicSharedMemorySize, SMEM1);
    cudaFuncSetAttribute(gemm_hmma<0>, cudaFuncAttributeMaxDynamicSharedMemorySize, SMEM);
    cudaFuncSetAttribute(gemm_hmma<1>, cudaFuncAttributeMaxDynamicSharedMemorySize, SMEM);

    // weight transposes (fp32 [K,N] -> fp16 [Npad,K])
    cvt_trans<<<dim3(HID / 32, FLAT / 32), dim3(32, 8)>>>(W1, (__half*)pW1, FLAT, HID);
    cvt_trans<<<dim3(HID / 32, HID / 32), dim3(32, 8)>>>(W2, (__half*)pW2, HID, HID);
    cvt_trans<<<dim3(NPAD / 32, HID / 32), dim3(32, 8)>>>(W3, (__half*)pW3, HID, NCLS);
    // MLP (grid.x = N-tiles so concurrent CTAs share A-tiles in L2)
    gemm1_fused<<<dim3(HID / 64, MROWS / 128), 256, SMEM1>>>(
        feat, (const __half*)pW1, b1, (__half*)pH1);
    gemm_hmma<0><<<dim3(HID / 64, MROWS / 128), 256, SMEM>>>(
        (const __half*)pH1, (const __half*)pW2, b2, pH2, nullptr, HID);
    gemm_hmma<1><<<dim3(NPAD / 64, MROWS / 128), 256, SMEM>>>(
        (const __half*)pH2, (const __half*)pW3, b3, d_out, mask, HID);
    (void)in_sizes; (void)n_in; (void)out_size;
}

// round 11
// speedup vs baseline: 3.4552x; 3.4552x over previous
#include <cuda_runtime.h>
#include <cuda_fp16.h>
#include <stdint.h>

// ---------------- problem constants ----------------
static constexpr int MROWS = 8192;          // 16*512
static constexpr int FLAT  = 12544;         // 7*7*256
static constexpr int HID   = 1024;
static constexpr int NCLS  = 81;
static constexpr int NPAD  = 128;

// ---------------- scratch (__device__ globals; no allocs allowed) ----------
__device__ __half g_featH[(size_t)MROWS * FLAT];   // compacted fp16 A
__device__ __half g_W1t[(size_t)HID * FLAT];       // [N,K] K-major
__device__ __half g_W2t[(size_t)HID * HID];
__device__ __half g_W3t[(size_t)NPAD * HID];       // rows 81..127 zero
__device__ __half g_H1[(size_t)MROWS * HID];
__device__ __half g_H2[(size_t)MROWS * HID];
__device__ int    g_idx[MROWS];
__device__ int    g_cnt;

// ---------------- helpers ----------------
__device__ __forceinline__ uint32_t smem_u32(const void* p) {
    uint32_t a;
    asm("{ .reg .u64 t; cvta.to.shared.u64 t, %1; cvt.u32.u64 %0, t; }" : "=r"(a) : "l"(p));
    return a;
}
#define SWZ(o) ((o) ^ (((o) >> 3) & 0x70))

__device__ __forceinline__ void cp16(uint32_t dst, const void* src) {
    asm volatile("cp.async.cg.shared.global [%0], [%1], 16;" :: "r"(dst), "l"(src) : "memory");
}
__device__ __forceinline__ void cp_commit() { asm volatile("cp.async.commit_group;" ::: "memory"); }
__device__ __forceinline__ void cp_wait1() { asm volatile("cp.async.wait_group 1;" ::: "memory"); }
__device__ __forceinline__ void cp_wait0() { asm volatile("cp.async.wait_group 0;" ::: "memory"); }

__device__ __forceinline__ void ldsm4(uint32_t (&r)[4], uint32_t addr) {
    asm volatile("ldmatrix.sync.aligned.m8n8.x4.shared.b16 {%0,%1,%2,%3}, [%4];"
        : "=r"(r[0]), "=r"(r[1]), "=r"(r[2]), "=r"(r[3]) : "r"(addr));
}
__device__ __forceinline__ void mma16816(float (&d)[4], const uint32_t (&a)[4],
                                         uint32_t b0, uint32_t b1) {
    asm volatile("mma.sync.aligned.m16n8k16.row.col.f32.f16.f16.f32 "
        "{%0,%1,%2,%3}, {%4,%5,%6,%7}, {%8,%9}, {%0,%1,%2,%3};"
        : "+f"(d[0]), "+f"(d[1]), "+f"(d[2]), "+f"(d[3])
        : "r"(a[0]), "r"(a[1]), "r"(a[2]), "r"(a[3]), "r"(b0), "r"(b1));
}

// ---------------- valid-row compaction (stable prefix scan) ----------------
__global__ void build_idx(const void* __restrict__ maskp,
                          int* __restrict__ idx, int* __restrict__ cntp) {
    __shared__ int sv[1024];
    __shared__ int s_is8, s_base;
    if (threadIdx.x == 0) {
        const unsigned char* m8 = (const unsigned char*)maskp;
        bool i8 = false;
        for (int i = 1; i < 256; ++i)
            if ((i & 3) && m8[i]) i8 = true;
        s_is8 = i8 ? 1 : 0;
        s_base = 0;
    }
    __syncthreads();
    const int is8 = s_is8;
    for (int chunk = 0; chunk < MROWS; chunk += 1024) {
        int r = chunk + threadIdx.x;
        int v = is8 ? (((const unsigned char*)maskp)[r] != 0)
                    : (((const int*)maskp)[r] != 0);
        sv[threadIdx.x] = v;
        __syncthreads();
        for (int off = 1; off < 1024; off <<= 1) {
            int t = (threadIdx.x >= off) ? sv[threadIdx.x - off] : 0;
            __syncthreads();
            sv[threadIdx.x] += t;
            __syncthreads();
        }
        if (v) idx[s_base + sv[threadIdx.x] - 1] = r;
        __syncthreads();
        if (threadIdx.x == 1023) s_base += sv[1023];
        __syncthreads();
    }
    if (threadIdx.x == 1023) *cntp = s_base;
}

// ---------------- gather + fp32->fp16 conversion (valid rows only) --------
__global__ void cvt_gather(const float* __restrict__ feat, __half* __restrict__ out,
                           const int* __restrict__ idx, const int* __restrict__ cntp) {
    int r = blockIdx.x;
    if (r >= *cntp) return;
    const float4* in = (const float4*)(feat + (size_t)idx[r] * FLAT);
    uint2* o = (uint2*)(out + (size_t)r * FLAT);
    for (int i = threadIdx.x; i < FLAT / 4; i += blockDim.x) {
        float4 v = in[i];
        __half2 a = __floats2half2_rn(v.x, v.y), b = __floats2half2_rn(v.z, v.w);
        o[i] = make_uint2(*(uint32_t*)&a, *(uint32_t*)&b);
    }
}

// W[K,N] fp32 -> Wt[Npad,K] fp16 (zero-pad n>=N). grid(Npad/32, K/32), block(32,8)
__global__ void cvt_trans(const float* __restrict__ W, __half* __restrict__ Wt, int K, int N) {
    __shared__ float t[32][33];
    int n0 = blockIdx.x * 32, k0 = blockIdx.y * 32;
    int tx = threadIdx.x, ty = threadIdx.y;
    #pragma unroll
    for (int i = 0; i < 32; i += 8) {
        int n = n0 + tx;
        t[ty + i][tx] = (n < N) ? W[(size_t)(k0 + ty + i) * N + n] : 0.f;
    }
    __syncthreads();
    #pragma unroll
    for (int i = 0; i < 32; i += 8)
        Wt[(size_t)(n0 + ty + i) * K + k0 + tx] = __float2half_rn(t[tx][ty + i]);
}

// ---------------- HMMA GEMM: C = post(A[Mc,K] @ Wt[N,K]^T + bias) ----------
// BM=128, BN=64, BK=64. 256 thr = 8 warps (4Mx2N), warp tile 32x32, occ 3.
// Operates on COMPACTED rows; CTAs beyond padded count early-exit.
// MODE 0: relu, fp16 out (stride HID).  MODE 1: scatter via idx, fp32 out (stride NCLS).
template <int MODE>
__global__ void __launch_bounds__(256, 3)
gemm_hmma(const __half* __restrict__ A, const __half* __restrict__ Wt,
          const float* __restrict__ bias, void* __restrict__ outp,
          const int* __restrict__ idx, const int* __restrict__ cntp, int K) {
    constexpr int A_BYTES = 128 * 128;
    constexpr int B_BYTES = 64 * 128;
    constexpr int STAGE   = A_BYTES + B_BYTES;   // 24 KB

    const int cnt = *cntp;
    const int m0 = blockIdx.y * 128;
    if (m0 >= ((cnt + 127) & ~127)) return;

    extern __shared__ char smem[];
    const uint32_t tiles = smem_u32(smem);

    const int tid = threadIdx.x, wid = tid >> 5, lid = tid & 31;
    const int n0 = blockIdx.x * 64;
    const int wm = (wid >> 1) * 32, wn = (wid & 1) * 32;
    const int KC = K >> 6;

    float acc[2][4][4];
    #pragma unroll
    for (int a = 0; a < 2; ++a)
        #pragma unroll
        for (int b = 0; b < 4; ++b)
            #pragma unroll
            for (int c = 0; c < 4; ++c) acc[a][b][c] = 0.f;

    auto load_stage = [&](int c) {
        const uint32_t sA = tiles + (uint32_t)(c % 3) * STAGE, sB = sA + A_BYTES;
        const __half* Ab = A + (size_t)m0 * K + (c << 6);
        const __half* Bb = Wt + (size_t)n0 * K + (c << 6);
        #pragma unroll
        for (int i = 0; i < 4; ++i) {
            int op = tid + i * 256, row = op >> 3, seg = op & 7;
            cp16(sA + SWZ((uint32_t)(row * 128 + seg * 16)), Ab + (size_t)row * K + seg * 8);
        }
        #pragma unroll
        for (int i = 0; i < 2; ++i) {
            int op = tid + i * 256, row = op >> 3, seg = op & 7;
            cp16(sB + SWZ((uint32_t)(row * 128 + seg * 16)), Bb + (size_t)row * K + seg * 8);
        }
        cp_commit();
    };

    load_stage(0);
    load_stage(1);

    const int lrow = lid & 15, lkh = lid >> 4;
    for (int c = 0; c < KC; ++c) {
        if (c >= KC - 1) cp_wait0(); else cp_wait1();
        __syncthreads();
        if (c + 2 < KC) load_stage(c + 2);
        const uint32_t sA = tiles + (uint32_t)(c % 3) * STAGE, sB = sA + A_BYTES;
        #pragma unroll
        for (int k0 = 0; k0 < 64; k0 += 16) {
            uint32_t bfr[2][4];
            #pragma unroll
            for (int nn = 0; nn < 2; ++nn) {
                uint32_t off = (uint32_t)((wn + nn * 16 + lrow) * 128 + (k0 + lkh * 8) * 2);
                ldsm4(bfr[nn], sB + SWZ(off));
            }
            #pragma unroll
            for (int ms = 0; ms < 2; ++ms) {
                uint32_t afr[4];
                uint32_t off = (uint32_t)((wm + ms * 16 + lrow) * 128 + (k0 + lkh * 8) * 2);
                ldsm4(afr, sA + SWZ(off));
                #pragma unroll
                for (int ns = 0; ns < 4; ++ns)
                    mma16816(acc[ms][ns], afr, bfr[ns >> 1][ns & 1], bfr[ns >> 1][(ns & 1) + 2]);
            }
        }
    }

    #pragma unroll
    for (int ms = 0; ms < 2; ++ms) {
        const int r0 = m0 + wm + ms * 16 + (lid >> 2);
        #pragma unroll
        for (int ns = 0; ns < 4; ++ns) {
            const int col = n0 + wn + ns * 8 + 2 * (lid & 3);
            if (MODE == 0) {
                float bx = bias[col], by = bias[col + 1];
                __half* o = (__half*)outp;
                *(__half2*)(o + (size_t)r0 * HID + col) =
                    __floats2half2_rn(fmaxf(acc[ms][ns][0] + bx, 0.f),
                                      fmaxf(acc[ms][ns][1] + by, 0.f));
                *(__half2*)(o + (size_t)(r0 + 8) * HID + col) =
                    __floats2half2_rn(fmaxf(acc[ms][ns][2] + bx, 0.f),
                                      fmaxf(acc[ms][ns][3] + by, 0.f));
            } else {
                float* o = (float*)outp;
                #pragma unroll
                for (int h = 0; h < 2; ++h) {
                    const int rr = r0 + h * 8;
                    if (rr < cnt) {
                        const int orow = idx[rr];
                        if (col < NCLS)
                            o[(size_t)orow * NCLS + col] = acc[ms][ns][2 * h] + bias[col];
                        if (col + 1 < NCLS)
                            o[(size_t)orow * NCLS + col + 1] = acc[ms][ns][2 * h + 1] + bias[col + 1];
                    }
                }
            }
        }
    }
}

// ---------------- launcher ----------------
extern "C" void kernel_launch(void* const* d_in, const int* in_sizes, int n_in,
                              void* d_out, int out_size) {
    const float* feat = (const float*)d_in[0];
    const void*  mask = d_in[1];
    const float* W1 = (const float*)d_in[2]; const float* b1 = (const float*)d_in[3];
    const float* W2 = (const float*)d_in[4]; const float* b2 = (const float*)d_in[5];
    const float* W3 = (const float*)d_in[6]; const float* b3 = (const float*)d_in[7];

    void *pF, *pW1, *pW2, *pW3, *pH1, *pH2, *pIdx, *pCnt;
    cudaGetSymbolAddress(&pF,  g_featH);
    cudaGetSymbolAddress(&pW1, g_W1t);
    cudaGetSymbolAddress(&pW2, g_W2t);
    cudaGetSymbolAddress(&pW3, g_W3t);
    cudaGetSymbolAddress(&pH1, g_H1);
    cudaGetSymbolAddress(&pH2, g_H2);
    cudaGetSymbolAddress(&pIdx, g_idx);
    cudaGetSymbolAddress(&pCnt, g_cnt);

    constexpr int SMEM = 3 * (128 * 128 + 64 * 128);   // 72 KB
    cudaFuncSetAttribute(gemm_hmma<0>, cudaFuncAttributeMaxDynamicSharedMemorySize, SMEM);
    cudaFuncSetAttribute(gemm_hmma<1>, cudaFuncAttributeMaxDynamicSharedMemorySize, SMEM);

    // output zeros (invalid rows stay 0)
    cudaMemsetAsync(d_out, 0, (size_t)out_size * sizeof(float));
    // valid-row compaction
    build_idx<<<1, 1024>>>(mask, (int*)pIdx, (int*)pCnt);
    // gather + fp32->fp16 (valid rows only)
    cvt_gather<<<MROWS, 256>>>(feat, (__half*)pF, (const int*)pIdx, (const int*)pCnt);
    // weight transposes (fp32 [K,N] -> fp16 [Npad,K])
    cvt_trans<<<dim3(HID / 32, FLAT / 32), dim3(32, 8)>>>(W1, (__half*)pW1, FLAT, HID);
    cvt_trans<<<dim3(HID / 32, HID / 32), dim3(32, 8)>>>(W2, (__half*)pW2, HID, HID);
    cvt_trans<<<dim3(NPAD / 32, HID / 32), dim3(32, 8)>>>(W3, (__half*)pW3, HID, NCLS);
    // MLP on compacted rows (grid.x = N-tiles so concurrent CTAs share A via L2)
    gemm_hmma<0><<<dim3(HID / 64, MROWS / 128), 256, SMEM>>>(
        (const __half*)pF, (const __half*)pW1, b1, pH1,
        (const int*)pIdx, (const int*)pCnt, FLAT);
    gemm_hmma<0><<<dim3(HID / 64, MROWS / 128), 256, SMEM>>>(
        (const __half*)pH1, (const __half*)pW2, b2, pH2,
        (const int*)pIdx, (const int*)pCnt, HID);
    gemm_hmma<1><<<dim3(NPAD / 64, MROWS / 128), 256, SMEM>>>(
        (const __half*)pH2, (const __half*)pW3, b3, d_out,
        (const int*)pIdx, (const int*)pCnt, HID);
    (void)in_sizes; (void)n_in;
}

// round 12
// speedup vs baseline: 4.0004x; 1.1578x over previous
#include <cuda_runtime.h>
#include <cuda_fp16.h>
#include <stdint.h>

// ---------------- problem constants ----------------
static constexpr int MROWS = 8192;          // 16*512
static constexpr int FLAT  = 12544;         // 7*7*256
static constexpr int HID   = 1024;
static constexpr int NCLS  = 81;
static constexpr int NPAD  = 128;

// ---------------- scratch (__device__ globals; no allocs allowed) ----------
__device__ __half g_featH[(size_t)MROWS * FLAT];   // compacted fp16 A
__device__ __half g_W1t[(size_t)HID * FLAT];       // [N,K] K-major
__device__ __half g_W2t[(size_t)HID * HID];
__device__ __half g_W3t[(size_t)NPAD * HID];       // rows 81..127 zero
__device__ __half g_H1[(size_t)MROWS * HID];
__device__ __half g_H2[(size_t)MROWS * HID];
__device__ int    g_idx[MROWS];
__device__ int    g_cnt;

// ---------------- helpers ----------------
__device__ __forceinline__ uint32_t smem_u32(const void* p) {
    uint32_t a;
    asm("{ .reg .u64 t; cvta.to.shared.u64 t, %1; cvt.u32.u64 %0, t; }" : "=r"(a) : "l"(p));
    return a;
}
#define SWZ(o) ((o) ^ (((o) >> 3) & 0x70))

__device__ __forceinline__ void cp16(uint32_t dst, const void* src) {
    asm volatile("cp.async.cg.shared.global [%0], [%1], 16;" :: "r"(dst), "l"(src) : "memory");
}
__device__ __forceinline__ void cp_commit() { asm volatile("cp.async.commit_group;" ::: "memory"); }
__device__ __forceinline__ void cp_wait1() { asm volatile("cp.async.wait_group 1;" ::: "memory"); }
__device__ __forceinline__ void cp_wait0() { asm volatile("cp.async.wait_group 0;" ::: "memory"); }

__device__ __forceinline__ void ldsm4(uint32_t (&r)[4], uint32_t addr) {
    asm volatile("ldmatrix.sync.aligned.m8n8.x4.shared.b16 {%0,%1,%2,%3}, [%4];"
        : "=r"(r[0]), "=r"(r[1]), "=r"(r[2]), "=r"(r[3]) : "r"(addr));
}
__device__ __forceinline__ void mma16816(float (&d)[4], const uint32_t (&a)[4],
                                         uint32_t b0, uint32_t b1) {
    asm volatile("mma.sync.aligned.m16n8k16.row.col.f32.f16.f16.f32 "
        "{%0,%1,%2,%3}, {%4,%5,%6,%7}, {%8,%9}, {%0,%1,%2,%3};"
        : "+f"(d[0]), "+f"(d[1]), "+f"(d[2]), "+f"(d[3])
        : "r"(a[0]), "r"(a[1]), "r"(a[2]), "r"(a[3]), "r"(b0), "r"(b1));
}

// ---------------- valid-row compaction (ballot scan, stable) ----------------
__global__ void build_idx(const void* __restrict__ maskp,
                          int* __restrict__ idx, int* __restrict__ cntp) {
    __shared__ int swarp[32];
    __shared__ int s_is8, s_base, s_total;
    const int tid = threadIdx.x, wid = tid >> 5, lane = tid & 31;
    if (tid == 0) {
        const unsigned char* m8 = (const unsigned char*)maskp;
        bool i8 = false;
        for (int i = 1; i < 256; ++i)
            if ((i & 3) && m8[i]) i8 = true;
        s_is8 = i8 ? 1 : 0;
        s_base = 0;
    }
    __syncthreads();
    const int is8 = s_is8;
    for (int chunk = 0; chunk < MROWS; chunk += 1024) {
        const int r = chunk + tid;
        const int v = is8 ? (((const unsigned char*)maskp)[r] != 0)
                          : (((const int*)maskp)[r] != 0);
        const unsigned bal = __ballot_sync(0xFFFFFFFFu, v);
        const int lanePre = __popc(bal & ((1u << lane) - 1u));
        if (lane == 0) swarp[wid] = __popc(bal);
        __syncthreads();
        if (wid == 0) {
            int orig = swarp[lane], x = orig;
            #pragma unroll
            for (int off = 1; off < 32; off <<= 1) {
                int y = __shfl_up_sync(0xFFFFFFFFu, x, off);
                if (lane >= off) x += y;
            }
            swarp[lane] = x - orig;           // exclusive prefix
            if (lane == 31) s_total = x;
        }
        __syncthreads();
        if (v) idx[s_base + swarp[wid] + lanePre] = r;
        __syncthreads();
        if (tid == 0) s_base += s_total;
        __syncthreads();
    }
    if (tid == 0) *cntp = s_base;
}

// ---------------- gather + fp32->fp16 conversion (valid rows only) --------
__global__ void cvt_gather(const float* __restrict__ feat, __half* __restrict__ out,
                           const int* __restrict__ idx, const int* __restrict__ cntp) {
    int r = blockIdx.x;
    if (r >= *cntp) return;
    const float4* in = (const float4*)(feat + (size_t)idx[r] * FLAT);
    uint2* o = (uint2*)(out + (size_t)r * FLAT);
    for (int i = threadIdx.x; i < FLAT / 4; i += blockDim.x) {
        float4 v = in[i];
        __half2 a = __floats2half2_rn(v.x, v.y), b = __floats2half2_rn(v.z, v.w);
        o[i] = make_uint2(*(uint32_t*)&a, *(uint32_t*)&b);
    }
}

// W[K,N] fp32 -> Wt[Npad,K] fp16 (zero-pad n>=N). grid(Npad/32, K/32), block(32,8)
__global__ void cvt_trans(const float* __restrict__ W, __half* __restrict__ Wt, int K, int N) {
    __shared__ float t[32][33];
    int n0 = blockIdx.x * 32, k0 = blockIdx.y * 32;
    int tx = threadIdx.x, ty = threadIdx.y;
    #pragma unroll
    for (int i = 0; i < 32; i += 8) {
        int n = n0 + tx;
        t[ty + i][tx] = (n < N) ? W[(size_t)(k0 + ty + i) * N + n] : 0.f;
    }
    __syncthreads();
    #pragma unroll
    for (int i = 0; i < 32; i += 8)
        Wt[(size_t)(n0 + ty + i) * K + k0 + tx] = __float2half_rn(t[tx][ty + i]);
}

// ---------------- HMMA GEMM: C = post(A[Mc,K] @ Wt[N,K]^T + bias) ----------
// BM=64, BN=64, BK=64. 128 thr = 4 warps (2Mx2N), warp tile 32x32, acc=32.
// 3-stage cp.async (48 KB) -> 4 CTAs/SM. Small tiles cut wave quantization.
// Compacted rows; CTAs beyond padded count early-exit.
// MODE 0: relu, fp16 out (stride HID).  MODE 1: scatter via idx, fp32 out (stride NCLS).
template <int MODE>
__global__ void __launch_bounds__(128, 4)
gemm_hmma(const __half* __restrict__ A, const __half* __restrict__ Wt,
          const float* __restrict__ bias, void* __restrict__ outp,
          const int* __restrict__ idx, const int* __restrict__ cntp, int K) {
    constexpr int A_BYTES = 64 * 128;
    constexpr int B_BYTES = 64 * 128;
    constexpr int STAGE   = A_BYTES + B_BYTES;   // 16 KB

    const int cnt = *cntp;
    const int m0 = blockIdx.y * 64;
    if (m0 >= ((cnt + 63) & ~63)) return;

    extern __shared__ char smem[];
    const uint32_t tiles = smem_u32(smem);

    const int tid = threadIdx.x, wid = tid >> 5, lid = tid & 31;
    const int n0 = blockIdx.x * 64;
    const int wm = (wid >> 1) * 32, wn = (wid & 1) * 32;
    const int KC = K >> 6;

    float acc[2][4][4];
    #pragma unroll
    for (int a = 0; a < 2; ++a)
        #pragma unroll
        for (int b = 0; b < 4; ++b)
            #pragma unroll
            for (int c = 0; c < 4; ++c) acc[a][b][c] = 0.f;

    auto load_stage = [&](int c) {
        const uint32_t sA = tiles + (uint32_t)(c % 3) * STAGE, sB = sA + A_BYTES;
        const __half* Ab = A + (size_t)m0 * K + (c << 6);
        const __half* Bb = Wt + (size_t)n0 * K + (c << 6);
        #pragma unroll
        for (int i = 0; i < 4; ++i) {          // A: 512 16B-ops / 128 thr
            int op = tid + i * 128, row = op >> 3, seg = op & 7;
            cp16(sA + SWZ((uint32_t)(row * 128 + seg * 16)), Ab + (size_t)row * K + seg * 8);
        }
        #pragma unroll
        for (int i = 0; i < 4; ++i) {          // B: 512 16B-ops
            int op = tid + i * 128, row = op >> 3, seg = op & 7;
            cp16(sB + SWZ((uint32_t)(row * 128 + seg * 16)), Bb + (size_t)row * K + seg * 8);
        }
        cp_commit();
    };

    load_stage(0);
    load_stage(1);

    const int lrow = lid & 15, lkh = lid >> 4;
    for (int c = 0; c < KC; ++c) {
        if (c >= KC - 1) cp_wait0(); else cp_wait1();
        __syncthreads();
        if (c + 2 < KC) load_stage(c + 2);
        const uint32_t sA = tiles + (uint32_t)(c % 3) * STAGE, sB = sA + A_BYTES;
        #pragma unroll
        for (int k0 = 0; k0 < 64; k0 += 16) {
            uint32_t bfr[2][4];
            #pragma unroll
            for (int nn = 0; nn < 2; ++nn) {
                uint32_t off = (uint32_t)((wn + nn * 16 + lrow) * 128 + (k0 + lkh * 8) * 2);
                ldsm4(bfr[nn], sB + SWZ(off));
            }
            #pragma unroll
            for (int ms = 0; ms < 2; ++ms) {
                uint32_t afr[4];
                uint32_t off = (uint32_t)((wm + ms * 16 + lrow) * 128 + (k0 + lkh * 8) * 2);
                ldsm4(afr, sA + SWZ(off));
                #pragma unroll
                for (int ns = 0; ns < 4; ++ns)
                    mma16816(acc[ms][ns], afr, bfr[ns >> 1][ns & 1], bfr[ns >> 1][(ns & 1) + 2]);
            }
        }
    }

    #pragma unroll
    for (int ms = 0; ms < 2; ++ms) {
        const int r0 = m0 + wm + ms * 16 + (lid >> 2);
        #pragma unroll
        for (int ns = 0; ns < 4; ++ns) {
            const int col = n0 + wn + ns * 8 + 2 * (lid & 3);
            if (MODE == 0) {
                float bx = bias[col], by = bias[col + 1];
                __half* o = (__half*)outp;
                *(__half2*)(o + (size_t)r0 * HID + col) =
                    __floats2half2_rn(fmaxf(acc[ms][ns][0] + bx, 0.f),
                                      fmaxf(acc[ms][ns][1] + by, 0.f));
                *(__half2*)(o + (size_t)(r0 + 8) * HID + col) =
                    __floats2half2_rn(fmaxf(acc[ms][ns][2] + bx, 0.f),
                                      fmaxf(acc[ms][ns][3] + by, 0.f));
            } else {
                float* o = (float*)outp;
                #pragma unroll
                for (int h = 0; h < 2; ++h) {
                    const int rr = r0 + h * 8;
                    if (rr < cnt) {
                        const int orow = idx[rr];
                        if (col < NCLS)
                            o[(size_t)orow * NCLS + col] = acc[ms][ns][2 * h] + bias[col];
                        if (col + 1 < NCLS)
                            o[(size_t)orow * NCLS + col + 1] = acc[ms][ns][2 * h + 1] + bias[col + 1];
                    }
                }
            }
        }
    }
}

// ---------------- launcher ----------------
extern "C" void kernel_launch(void* const* d_in, const int* in_sizes, int n_in,
                              void* d_out, int out_size) {
    const float* feat = (const float*)d_in[0];
    const void*  mask = d_in[1];
    const float* W1 = (const float*)d_in[2]; const float* b1 = (const float*)d_in[3];
    const float* W2 = (const float*)d_in[4]; const float* b2 = (const float*)d_in[5];
    const float* W3 = (const float*)d_in[6]; const float* b3 = (const float*)d_in[7];

    void *pF, *pW1, *pW2, *pW3, *pH1, *pH2, *pIdx, *pCnt;
    cudaGetSymbolAddress(&pF,  g_featH);
    cudaGetSymbolAddress(&pW1, g_W1t);
    cudaGetSymbolAddress(&pW2, g_W2t);
    cudaGetSymbolAddress(&pW3, g_W3t);
    cudaGetSymbolAddress(&pH1, g_H1);
    cudaGetSymbolAddress(&pH2, g_H2);
    cudaGetSymbolAddress(&pIdx, g_idx);
    cudaGetSymbolAddress(&pCnt, g_cnt);

    constexpr int SMEM = 3 * (64 * 128 + 64 * 128);   // 48 KB
    cudaFuncSetAttribute(gemm_hmma<0>, cudaFuncAttributeMaxDynamicSharedMemorySize, SMEM);
    cudaFuncSetAttribute(gemm_hmma<1>, cudaFuncAttributeMaxDynamicSharedMemorySize, SMEM);

    // output zeros (invalid rows stay 0)
    cudaMemsetAsync(d_out, 0, (size_t)out_size * sizeof(float));
    // valid-row compaction
    build_idx<<<1, 1024>>>(mask, (int*)pIdx, (int*)pCnt);
    // gather + fp32->fp16 (valid rows only)
    cvt_gather<<<MROWS, 256>>>(feat, (__half*)pF, (const int*)pIdx, (const int*)pCnt);
    // weight transposes (fp32 [K,N] -> fp16 [Npad,K])
    cvt_trans<<<dim3(HID / 32, FLAT / 32), dim3(32, 8)>>>(W1, (__half*)pW1, FLAT, HID);
    cvt_trans<<<dim3(HID / 32, HID / 32), dim3(32, 8)>>>(W2, (__half*)pW2, HID, HID);
    cvt_trans<<<dim3(NPAD / 32, HID / 32), dim3(32, 8)>>>(W3, (__half*)pW3, HID, NCLS);
    // MLP on compacted rows (grid.x = N-tiles so concurrent CTAs share A via L2)
    gemm_hmma<0><<<dim3(HID / 64, MROWS / 64), 128, SMEM>>>(
        (const __half*)pF, (const __half*)pW1, b1, pH1,
        (const int*)pIdx, (const int*)pCnt, FLAT);
    gemm_hmma<0><<<dim3(HID / 64, MROWS / 64), 128, SMEM>>>(
        (const __half*)pH1, (const __half*)pW2, b2, pH2,
        (const int*)pIdx, (const int*)pCnt, HID);
    gemm_hmma<1><<<dim3(NPAD / 64, MROWS / 64), 128, SMEM>>>(
        (const __half*)pH2, (const __half*)pW3, b3, d_out,
        (const int*)pIdx, (const int*)pCnt, HID);
    (void)in_sizes; (void)n_in;
}

// round 13
// speedup vs baseline: 4.0085x; 1.0020x over previous
#include <cuda_runtime.h>
#include <cuda_fp16.h>
#include <stdint.h>

// ---------------- problem constants ----------------
static constexpr int MROWS = 8192;          // 16*512
static constexpr int FLAT  = 12544;         // 7*7*256
static constexpr int HID   = 1024;
static constexpr int NCLS  = 81;
static constexpr int NPAD  = 128;

// prep kernel block ranges
static constexpr int T1 = (HID / 32) * (FLAT / 32);   // 12544 W1 tiles
static constexpr int T2 = (HID / 32) * (HID / 32);    // 1024  W2 tiles
static constexpr int T3 = (NPAD / 32) * (HID / 32);   // 128   W3 tiles

// ---------------- scratch (__device__ globals; no allocs allowed) ----------
__device__ __half g_featH[(size_t)MROWS * FLAT];   // compacted fp16 A
__device__ __half g_W1t[(size_t)HID * FLAT];       // [N,K] K-major
__device__ __half g_W2t[(size_t)HID * HID];
__device__ __half g_W3t[(size_t)NPAD * HID];       // rows 81..127 zero
__device__ __half g_H1[(size_t)MROWS * HID];
__device__ __half g_H2[(size_t)MROWS * HID];
__device__ int    g_idx[MROWS];
__device__ int    g_cnt;

// ---------------- helpers ----------------
__device__ __forceinline__ uint32_t smem_u32(const void* p) {
    uint32_t a;
    asm("{ .reg .u64 t; cvta.to.shared.u64 t, %1; cvt.u32.u64 %0, t; }" : "=r"(a) : "l"(p));
    return a;
}
#define SWZ(o) ((o) ^ (((o) >> 3) & 0x70))

__device__ __forceinline__ void cp16(uint32_t dst, const void* src) {
    asm volatile("cp.async.cg.shared.global [%0], [%1], 16;" :: "r"(dst), "l"(src) : "memory");
}
__device__ __forceinline__ void cp_commit() { asm volatile("cp.async.commit_group;" ::: "memory"); }
__device__ __forceinline__ void cp_wait1() { asm volatile("cp.async.wait_group 1;" ::: "memory"); }
__device__ __forceinline__ void cp_wait0() { asm volatile("cp.async.wait_group 0;" ::: "memory"); }

__device__ __forceinline__ void ldsm4(uint32_t (&r)[4], uint32_t addr) {
    asm volatile("ldmatrix.sync.aligned.m8n8.x4.shared.b16 {%0,%1,%2,%3}, [%4];"
        : "=r"(r[0]), "=r"(r[1]), "=r"(r[2]), "=r"(r[3]) : "r"(addr));
}
__device__ __forceinline__ void mma16816(float (&d)[4], const uint32_t (&a)[4],
                                         uint32_t b0, uint32_t b1) {
    asm volatile("mma.sync.aligned.m16n8k16.row.col.f32.f16.f16.f32 "
        "{%0,%1,%2,%3}, {%4,%5,%6,%7}, {%8,%9}, {%0,%1,%2,%3};"
        : "+f"(d[0]), "+f"(d[1]), "+f"(d[2]), "+f"(d[3])
        : "r"(a[0]), "r"(a[1]), "r"(a[2]), "r"(a[3]), "r"(b0), "r"(b1));
}

// ---------------- valid-row compaction (ballot scan, stable) ----------------
__global__ void build_idx(const void* __restrict__ maskp,
                          int* __restrict__ idx, int* __restrict__ cntp) {
    __shared__ int swarp[32];
    __shared__ int s_is8, s_base, s_total;
    const int tid = threadIdx.x, wid = tid >> 5, lane = tid & 31;
    if (tid == 0) {
        const unsigned char* m8 = (const unsigned char*)maskp;
        bool i8 = false;
        for (int i = 1; i < 256; ++i)
            if ((i & 3) && m8[i]) i8 = true;
        s_is8 = i8 ? 1 : 0;
        s_base = 0;
    }
    __syncthreads();
    const int is8 = s_is8;
    for (int chunk = 0; chunk < MROWS; chunk += 1024) {
        const int r = chunk + tid;
        const int v = is8 ? (((const unsigned char*)maskp)[r] != 0)
                          : (((const int*)maskp)[r] != 0);
        const unsigned bal = __ballot_sync(0xFFFFFFFFu, v);
        const int lanePre = __popc(bal & ((1u << lane) - 1u));
        if (lane == 0) swarp[wid] = __popc(bal);
        __syncthreads();
        if (wid == 0) {
            int orig = swarp[lane], x = orig;
            #pragma unroll
            for (int off = 1; off < 32; off <<= 1) {
                int y = __shfl_up_sync(0xFFFFFFFFu, x, off);
                if (lane >= off) x += y;
            }
            swarp[lane] = x - orig;           // exclusive prefix
            if (lane == 31) s_total = x;
        }
        __syncthreads();
        if (v) idx[s_base + swarp[wid] + lanePre] = r;
        __syncthreads();
        if (tid == 0) s_base += s_total;
        __syncthreads();
    }
    if (tid == 0) *cntp = s_base;
}

// ---------------- fused prep: row gather+cvt AND all weight transposes -----
// blocks [0, MROWS)              : gather+convert valid feature rows
// blocks [MROWS, MROWS+T1)       : W1 transpose tiles
// blocks [.., +T2)               : W2 transpose tiles
// blocks [.., +T3)               : W3 transpose tiles (zero-padded to NPAD)
__global__ void __launch_bounds__(256)
prep(const float* __restrict__ feat, const int* __restrict__ idx,
     const int* __restrict__ cntp, __half* __restrict__ fOut,
     const float* __restrict__ W1, const float* __restrict__ W2,
     const float* __restrict__ W3, __half* __restrict__ W1t,
     __half* __restrict__ W2t, __half* __restrict__ W3t) {
    __shared__ float t[32][33];
    int b = blockIdx.x;
    const int tid = threadIdx.x;

    if (b < MROWS) {                              // ---- gather role ----
        if (b >= *cntp) return;
        const float4* in = (const float4*)(feat + (size_t)idx[b] * FLAT);
        uint2* o = (uint2*)(fOut + (size_t)b * FLAT);
        for (int i = tid; i < FLAT / 4; i += 256) {
            float4 v = in[i];
            __half2 a = __floats2half2_rn(v.x, v.y), bb = __floats2half2_rn(v.z, v.w);
            o[i] = make_uint2(*(uint32_t*)&a, *(uint32_t*)&bb);
        }
        return;
    }
    b -= MROWS;                                   // ---- transpose role ----
    const float* W; __half* Wt; int K, N, nx;
    if (b < T1)      { W = W1; Wt = W1t; K = FLAT; N = HID;  nx = HID / 32; }
    else if (b < T1 + T2) { b -= T1; W = W2; Wt = W2t; K = HID; N = HID; nx = HID / 32; }
    else             { b -= T1 + T2; W = W3; Wt = W3t; K = HID; N = NCLS; nx = NPAD / 32; }
    const int n0 = (b % nx) * 32, k0 = (b / nx) * 32;
    const int tx = tid & 31, ty = tid >> 5;
    #pragma unroll
    for (int i = 0; i < 32; i += 8) {
        int n = n0 + tx;
        t[ty + i][tx] = (n < N) ? W[(size_t)(k0 + ty + i) * N + n] : 0.f;
    }
    __syncthreads();
    #pragma unroll
    for (int i = 0; i < 32; i += 8)
        Wt[(size_t)(n0 + ty + i) * K + k0 + tx] = __float2half_rn(t[tx][ty + i]);
}

// ---------------- HMMA GEMM: C = post(A[Mc,K] @ Wt[N,K]^T + bias) ----------
// BM=64, BN=64, BK=64. 128 thr = 4 warps (2Mx2N), warp tile 32x32, acc=32.
// 3-stage cp.async (48 KB) -> 4 CTAs/SM. Compacted rows; extra CTAs early-exit.
// MODE 0: relu, fp16 out (stride HID).  MODE 1: scatter via idx, fp32 out (stride NCLS).
template <int MODE>
__global__ void __launch_bounds__(128, 4)
gemm_hmma(const __half* __restrict__ A, const __half* __restrict__ Wt,
          const float* __restrict__ bias, void* __restrict__ outp,
          const int* __restrict__ idx, const int* __restrict__ cntp, int K) {
    constexpr int A_BYTES = 64 * 128;
    constexpr int B_BYTES = 64 * 128;
    constexpr int STAGE   = A_BYTES + B_BYTES;   // 16 KB

    const int cnt = *cntp;
    const int m0 = blockIdx.y * 64;
    if (m0 >= ((cnt + 63) & ~63)) return;

    extern __shared__ char smem[];
    const uint32_t tiles = smem_u32(smem);

    const int tid = threadIdx.x, wid = tid >> 5, lid = tid & 31;
    const int n0 = blockIdx.x * 64;
    const int wm = (wid >> 1) * 32, wn = (wid & 1) * 32;
    const int KC = K >> 6;

    float acc[2][4][4];
    #pragma unroll
    for (int a = 0; a < 2; ++a)
        #pragma unroll
        for (int b = 0; b < 4; ++b)
            #pragma unroll
            for (int c = 0; c < 4; ++c) acc[a][b][c] = 0.f;

    auto load_stage = [&](int c) {
        const uint32_t sA = tiles + (uint32_t)(c % 3) * STAGE, sB = sA + A_BYTES;
        const __half* Ab = A + (size_t)m0 * K + (c << 6);
        const __half* Bb = Wt + (size_t)n0 * K + (c << 6);
        #pragma unroll
        for (int i = 0; i < 4; ++i) {
            int op = tid + i * 128, row = op >> 3, seg = op & 7;
            cp16(sA + SWZ((uint32_t)(row * 128 + seg * 16)), Ab + (size_t)row * K + seg * 8);
        }
        #pragma unroll
        for (int i = 0; i < 4; ++i) {
            int op = tid + i * 128, row = op >> 3, seg = op & 7;
            cp16(sB + SWZ((uint32_t)(row * 128 + seg * 16)), Bb + (size_t)row * K + seg * 8);
        }
        cp_commit();
    };

    load_stage(0);
    load_stage(1);

    const int lrow = lid & 15, lkh = lid >> 4;
    for (int c = 0; c < KC; ++c) {
        if (c >= KC - 1) cp_wait0(); else cp_wait1();
        __syncthreads();
        if (c + 2 < KC) load_stage(c + 2);
        const uint32_t sA = tiles + (uint32_t)(c % 3) * STAGE, sB = sA + A_BYTES;
        #pragma unroll
        for (int k0 = 0; k0 < 64; k0 += 16) {
            uint32_t bfr[2][4];
            #pragma unroll
            for (int nn = 0; nn < 2; ++nn) {
                uint32_t off = (uint32_t)((wn + nn * 16 + lrow) * 128 + (k0 + lkh * 8) * 2);
                ldsm4(bfr[nn], sB + SWZ(off));
            }
            #pragma unroll
            for (int ms = 0; ms < 2; ++ms) {
                uint32_t afr[4];
                uint32_t off = (uint32_t)((wm + ms * 16 + lrow) * 128 + (k0 + lkh * 8) * 2);
                ldsm4(afr, sA + SWZ(off));
                #pragma unroll
                for (int ns = 0; ns < 4; ++ns)
                    mma16816(acc[ms][ns], afr, bfr[ns >> 1][ns & 1], bfr[ns >> 1][(ns & 1) + 2]);
            }
        }
    }

    #pragma unroll
    for (int ms = 0; ms < 2; ++ms) {
        const int r0 = m0 + wm + ms * 16 + (lid >> 2);
        #pragma unroll
        for (int ns = 0; ns < 4; ++ns) {
            const int col = n0 + wn + ns * 8 + 2 * (lid & 3);
            if (MODE == 0) {
                float bx = bias[col], by = bias[col + 1];
                __half* o = (__half*)outp;
                *(__half2*)(o + (size_t)r0 * HID + col) =
                    __floats2half2_rn(fmaxf(acc[ms][ns][0] + bx, 0.f),
                                      fmaxf(acc[ms][ns][1] + by, 0.f));
                *(__half2*)(o + (size_t)(r0 + 8) * HID + col) =
                    __floats2half2_rn(fmaxf(acc[ms][ns][2] + bx, 0.f),
                                      fmaxf(acc[ms][ns][3] + by, 0.f));
            } else {
                float* o = (float*)outp;
                #pragma unroll
                for (int h = 0; h < 2; ++h) {
                    const int rr = r0 + h * 8;
                    if (rr < cnt) {
                        const int orow = idx[rr];
                        if (col < NCLS)
                            o[(size_t)orow * NCLS + col] = acc[ms][ns][2 * h] + bias[col];
                        if (col + 1 < NCLS)
                            o[(size_t)orow * NCLS + col + 1] = acc[ms][ns][2 * h + 1] + bias[col + 1];
                    }
                }
            }
        }
    }
}

// ---------------- launcher ----------------
extern "C" void kernel_launch(void* const* d_in, const int* in_sizes, int n_in,
                              void* d_out, int out_size) {
    const float* feat = (const float*)d_in[0];
    const void*  mask = d_in[1];
    const float* W1 = (const float*)d_in[2]; const float* b1 = (const float*)d_in[3];
    const float* W2 = (const float*)d_in[4]; const float* b2 = (const float*)d_in[5];
    const float* W3 = (const float*)d_in[6]; const float* b3 = (const float*)d_in[7];

    void *pF, *pW1, *pW2, *pW3, *pH1, *pH2, *pIdx, *pCnt;
    cudaGetSymbolAddress(&pF,  g_featH);
    cudaGetSymbolAddress(&pW1, g_W1t);
    cudaGetSymbolAddress(&pW2, g_W2t);
    cudaGetSymbolAddress(&pW3, g_W3t);
    cudaGetSymbolAddress(&pH1, g_H1);
    cudaGetSymbolAddress(&pH2, g_H2);
    cudaGetSymbolAddress(&pIdx, g_idx);
    cudaGetSymbolAddress(&pCnt, g_cnt);

    constexpr int SMEM = 3 * (64 * 128 + 64 * 128);   // 48 KB
    cudaFuncSetAttribute(gemm_hmma<0>, cudaFuncAttributeMaxDynamicSharedMemorySize, SMEM);
    cudaFuncSetAttribute(gemm_hmma<1>, cudaFuncAttributeMaxDynamicSharedMemorySize, SMEM);

    // output zeros (invalid rows stay 0)
    cudaMemsetAsync(d_out, 0, (size_t)out_size * sizeof(float));
    // valid-row compaction
    build_idx<<<1, 1024>>>(mask, (int*)pIdx, (int*)pCnt);
    // fused prep: gather+convert valid rows AND all 3 weight transposes
    prep<<<MROWS + T1 + T2 + T3, 256>>>(
        feat, (const int*)pIdx, (const int*)pCnt, (__half*)pF,
        W1, W2, W3, (__half*)pW1, (__half*)pW2, (__half*)pW3);
    // MLP on compacted rows (grid.x = N-tiles so concurrent CTAs share A via L2)
    gemm_hmma<0><<<dim3(HID / 64, MROWS / 64), 128, SMEM>>>(
        (const __half*)pF, (const __half*)pW1, b1, pH1,
        (const int*)pIdx, (const int*)pCnt, FLAT);
    gemm_hmma<0><<<dim3(HID / 64, MROWS / 64), 128, SMEM>>>(
        (const __half*)pH1, (const __half*)pW2, b2, pH2,
        (const int*)pIdx, (const int*)pCnt, HID);
    gemm_hmma<1><<<dim3(NPAD / 64, MROWS / 64), 128, SMEM>>>(
        (const __half*)pH2, (const __half*)pW3, b3, d_out,
        (const int*)pIdx, (const int*)pCnt, HID);
    (void)in_sizes; (void)n_in;
}